// round 11
// baseline (speedup 1.0000x reference)
#include <cuda_runtime.h>
#include <cuda_bf16.h>

// Inputs (metadata order):
//   d_in[0] input_values   float32 [1024]
//   d_in[1] weight_matrix  float32 [16384*16384] row-major
//   d_in[2] biases         float32 [16384]
//   d_in[3] act_ids        int32   [16384]   0=identity 1=relu 2=softsign
//   d_in[4] input_indices  int32   [1024]
//   d_in[5] output_indices int32   [256]
// Output: float32 [256]
//
// out[o] = act( sum_i in_vals[i] * W[in_idx[i], out_idx[o]] + bias[out_idx[o]] )
//
// Fine-grained single launch: CHUNKS (=4) CTAs per output, 256 threads each,
// one scattered W load per thread -> ~7 CTAs/SM, whole-chip balance, maximal
// loads-in-flight. Combine via relaxed float atomicAdd + one acq_rel arrival
// counter (NO threadfence / NO volatile spinning -- that was R3's mistake).
// The last-arriving CTA finalizes (bias + activation, pre-issued loads) and
// resets the scratch slots for the next stream-ordered graph replay.

#define BLOCK  256
#define CHUNKS 4
#define MAX_OUT 4096

__device__ float        g_accum[MAX_OUT];   // zero-init at module load
__device__ unsigned int g_count[MAX_OUT];   // zero-init at module load

__device__ __forceinline__ unsigned int atom_inc_acqrel(unsigned int* p, unsigned int v) {
    unsigned int old;
    asm volatile("atom.add.acq_rel.gpu.u32 %0, [%1], %2;"
                 : "=r"(old) : "l"(p), "r"(v) : "memory");
    return old;
}

__device__ __forceinline__ float ld_acquire_f32(const float* p) {
    float v;
    asm volatile("ld.acquire.gpu.f32 %0, [%1];" : "=f"(v) : "l"(p) : "memory");
    return v;
}

__global__ void __launch_bounds__(BLOCK)
fused_gather_kernel(const float* __restrict__ in_vals,
                    const float* __restrict__ W,
                    const float* __restrict__ bias,
                    const int*   __restrict__ act_ids,
                    const int*   __restrict__ in_idx,
                    const int*   __restrict__ out_idx,
                    float*       __restrict__ out,
                    int n_in, int N)
{
    const int c     = blockIdx.x;
    const int o     = c >> 2;               // output slot   (CHUNKS == 4)
    const int chunk = c & 3;                // slice within the dot product
    const int t     = threadIdx.x;
    const int i     = chunk * BLOCK + t;

    // Issue all front loads immediately; j-dependent finalize inputs are
    // prefetched by EVERY CTA (uniform, L2-warm) so the last CTA has them
    // in registers with no extra latency on its critical path.
    const int j = __ldg(&out_idx[o]);

    float p = 0.0f;
    if (i < n_in) {
        const int r = __ldg(&in_idx[i]);
        p = __ldg(&in_vals[i]) * __ldg(&W[r * N + j]);   // 32-bit addressing
    }
    const float b = __ldg(&bias[j]);
    const int   a = __ldg(&act_ids[j]);

    // warp reduce, then cross-warp combine (8 warps)
    #pragma unroll
    for (int off = 16; off > 0; off >>= 1)
        p += __shfl_xor_sync(0xFFFFFFFFu, p, off);

    __shared__ float sm[BLOCK / 32];
    const int lane = t & 31;
    const int wid  = t >> 5;
    if (lane == 0) sm[wid] = p;
    __syncthreads();

    if (t == 0) {
        float v = sm[0];
        #pragma unroll
        for (int w = 1; w < BLOCK / 32; w++) v += sm[w];

        // relaxed accumulate; the acq_rel counter below publishes it
        atomicAdd(&g_accum[o], v);
        const unsigned int old = atom_inc_acqrel(&g_count[o], 1u);
        if (old == CHUNKS - 1) {
            const float sum   = ld_acquire_f32(&g_accum[o]);
            const float total = sum + b;
            const float relu  = fmaxf(total, 0.0f);
            const float ssign = total / (1.0f + fabsf(total));
            out[o] = (a == 1) ? relu : ((a == 2) ? ssign : total);
            // reset scratch for next stream-ordered replay
            g_accum[o] = 0.0f;
            g_count[o] = 0u;
        }
    }
}

extern "C" void kernel_launch(void* const* d_in, const int* in_sizes, int n_in_args,
                              void* d_out, int out_size)
{
    const float* in_vals = (const float*)d_in[0];
    const float* W       = (const float*)d_in[1];
    const float* bias    = (const float*)d_in[2];
    const int*   act_ids = (const int*)  d_in[3];
    const int*   in_idx  = (const int*)  d_in[4];
    const int*   out_idx = (const int*)  d_in[5];
    float*       out     = (float*)      d_out;

    const int n_in = in_sizes[0];   // 1024
    const int N    = in_sizes[2];   // 16384 (bias length)

    fused_gather_kernel<<<out_size * CHUNKS, BLOCK>>>(
        in_vals, W, bias, act_ids, in_idx, out_idx, out, n_in, N);
}

// round 12
// speedup vs baseline: 1.3009x; 1.3009x over previous
#include <cuda_runtime.h>
#include <cuda_bf16.h>

// Inputs (metadata order):
//   d_in[0] input_values   float32 [1024]
//   d_in[1] weight_matrix  float32 [16384*16384] row-major
//   d_in[2] biases         float32 [16384]
//   d_in[3] act_ids        int32   [16384]   0=identity 1=relu 2=softsign
//   d_in[4] input_indices  int32   [1024]
//   d_in[5] output_indices int32   [256]
// Output: float32 [256]
//
// out[o] = act( sum_i in_vals[i] * W[in_idx[i], out_idx[o]] + bias[out_idx[o]] )
//
// FINAL DESIGN (floor-pinned): measured per-replay time is dominated by a
// ~6.66 us CUDA-graph replay overhead; every protocol-free single-launch
// kernel (1-wave or 2-wave alike) measures identically, while any multi-node
// or cross-CTA-protocol variant regresses. So: ONE kernel node, one CTA per
// output (grid=256, block=256), one int4+float4 metadata load per thread,
// 4 independent scattered W loads with 32-bit address math (row*16384+j <
// 2^28), bias/act prefetched before the reduction so the finalize tail is
// pure ALU, two-stage shuffle+smem reduction, inline activation select.

#define BLOCK 256

__global__ void __launch_bounds__(BLOCK, 4)
custom_network_kernel(const float* __restrict__ in_vals,
                      const float* __restrict__ W,
                      const float* __restrict__ bias,
                      const int*   __restrict__ act_ids,
                      const int*   __restrict__ in_idx,
                      const int*   __restrict__ out_idx,
                      float*       __restrict__ out,
                      int n_in, int N)
{
    const int t = threadIdx.x;
    const int j = __ldg(&out_idx[blockIdx.x]);   // uniform per CTA

    float p = 0.0f;

    if ((n_in & (4 * BLOCK - 1)) == 0) {
        // fast path: one int4 + one float4 metadata load, 4 W-gathers per tile
        const int4*   idx4 = (const int4*)in_idx;
        const float4* val4 = (const float4*)in_vals;
        const int tiles = n_in >> 10;            // n_in / (4*BLOCK)
        for (int ti = 0; ti < tiles; ti++) {
            const int base = ti * BLOCK + t;
            const int4   r4 = __ldg(&idx4[base]);
            const float4 v4 = __ldg(&val4[base]);
            const float w0 = __ldg(&W[r4.x * N + j]);
            const float w1 = __ldg(&W[r4.y * N + j]);
            const float w2 = __ldg(&W[r4.z * N + j]);
            const float w3 = __ldg(&W[r4.w * N + j]);
            p += v4.x * w0 + v4.y * w1 + v4.z * w2 + v4.w * w3;
        }
    } else {
        // generic path for arbitrary n_in
        for (int i = t; i < n_in; i += BLOCK) {
            const int r = __ldg(&in_idx[i]);
            p += __ldg(&in_vals[i]) * __ldg(&W[r * N + j]);
        }
    }

    // Prefetch finalize inputs BEFORE the reduction: their latency hides
    // under the shuffle/barrier tree, leaving a pure-ALU tail for lane 0.
    const float b = __ldg(&bias[j]);
    const int   a = __ldg(&act_ids[j]);

    // warp reduce (8 warps), then cross-warp combine
    #pragma unroll
    for (int off = 16; off > 0; off >>= 1)
        p += __shfl_xor_sync(0xFFFFFFFFu, p, off);

    __shared__ float sm[BLOCK / 32];
    const int lane = t & 31;
    const int wid  = t >> 5;
    if (lane == 0) sm[wid] = p;
    __syncthreads();

    if (wid == 0) {
        float v = (lane < BLOCK / 32) ? sm[lane] : 0.0f;
        #pragma unroll
        for (int off = 4; off > 0; off >>= 1)
            v += __shfl_xor_sync(0xFFFFFFFFu, v, off);

        if (lane == 0) {
            const float total = v + b;
            const float relu  = fmaxf(total, 0.0f);
            const float ssign = total / (1.0f + fabsf(total));
            out[blockIdx.x] = (a == 1) ? relu : ((a == 2) ? ssign : total);
        }
    }
}

extern "C" void kernel_launch(void* const* d_in, const int* in_sizes, int n_in_args,
                              void* d_out, int out_size)
{
    const float* in_vals = (const float*)d_in[0];
    const float* W       = (const float*)d_in[1];
    const float* bias    = (const float*)d_in[2];
    const int*   act_ids = (const int*)  d_in[3];
    const int*   in_idx  = (const int*)  d_in[4];
    const int*   out_idx = (const int*)  d_in[5];
    float*       out     = (float*)      d_out;

    const int n_in = in_sizes[0];   // 1024
    const int N    = in_sizes[2];   // 16384 (bias length)

    custom_network_kernel<<<out_size, BLOCK>>>(
        in_vals, W, bias, act_ids, in_idx, out_idx, out, n_in, N);
}